// round 7
// baseline (speedup 1.0000x reference)
#include <cuda_runtime.h>
#include <cuda_bf16.h>

#define IMH 4096
#define IMW 4096
#define RAD 8
#define BX 128
#define OUT_W 112
#define CHUNK 16
#define SEGH 512
#define NSTRIPS ((IMW + OUT_W - 1) / OUT_W)   // 37
#define NSEG (IMH / SEGH)                     // 8
#define EPSF 1e-4f
#define IRING 24

typedef unsigned long long ull;

// ~51.4 KB -> 4 CTAs/SM. Odd strides (129/113) keep row-indexed access
// conflict-free; vbuf stored as packed f32x2 (ull) -> LDS.64 feeds packed ALU.
struct SmemT {
    float i_ring[IRING][BX + 1];   // rows y0..y0+23 of i (HF center reads)
    ull   vb_ip [CHUNK][BX + 1];   // packed (vsum_i, vsum_p)
    ull   vb_pii[CHUNK][BX + 1];   // packed (vsum_pi, vsum_ii)
    float qbuf[CHUNK][OUT_W + 1];  // staged outputs for coalesced store
};

__device__ __forceinline__ ull f2_pack(float x, float y) {
    ull r; asm("mov.b64 %0, {%1, %2};" : "=l"(r) : "f"(x), "f"(y)); return r;
}
__device__ __forceinline__ float2 f2_unpack(ull v) {
    float2 t; asm("mov.b64 {%0, %1}, %2;" : "=f"(t.x), "=f"(t.y) : "l"(v)); return t;
}
__device__ __forceinline__ ull f2_add(ull a, ull b) {
    ull r; asm("add.rn.f32x2 %0, %1, %2;" : "=l"(r) : "l"(a), "l"(b)); return r;
}
__device__ __forceinline__ ull f2_fma(ull a, ull b, ull c) {
    ull r; asm("fma.rn.f32x2 %0, %1, %2, %3;" : "=l"(r) : "l"(a), "l"(b), "l"(c)); return r;
}

// FAST: whole 14-col range is x-interior AND whole chunk is y-interior -> N=289.
template<bool FAST>
__device__ __forceinline__ void hf_phase(SmemT& sm, int hr, int xbase,
                                         int y0, int y0m, int X0)
{
    const int y = y0 + hr;
    int sy = y0m + hr; if (sy >= IRING) sy -= IRING;
    int ny = 17;
    if (!FAST) ny = min(y + RAD, IMH - 1) - max(y - RAD, 0) + 1;

    const ull M1 = f2_pack(-1.0f, -1.0f);
    ull h_ip = 0ull, h_pii = 0ull;        // bit pattern of (0f,0f)
    #pragma unroll
    for (int d = -RAD; d <= RAD; ++d) {
        h_ip  = f2_add(h_ip,  sm.vb_ip [hr][xbase + d]);
        h_pii = f2_add(h_pii, sm.vb_pii[hr][xbase + d]);
    }
    #pragma unroll
    for (int j = 0; j < 14; ++j) {
        const int x = xbase + j;
        if (j > 0) {   // h += lead - trail  (add, then fma with -1)
            h_ip  = f2_fma(sm.vb_ip [hr][x - RAD - 1], M1,
                           f2_add(h_ip,  sm.vb_ip [hr][x + RAD]));
            h_pii = f2_fma(sm.vb_pii[hr][x - RAD - 1], M1,
                           f2_add(h_pii, sm.vb_pii[hr][x + RAD]));
        }
        float invN;
        if (FAST) {
            invN = 1.0f / 289.0f;
        } else {
            const int gx = X0 + x - RAD;
            const int nx = min(gx + RAD, IMW - 1) - max(gx - RAD, 0) + 1;
            invN = __fdividef(1.0f, (float)(ny * nx));
        }
        const float2 hip  = f2_unpack(h_ip);
        const float2 hpii = f2_unpack(h_pii);
        const float m_i  = hip.x  * invN;
        const float m_p  = hip.y  * invN;
        const float m_pi = hpii.x * invN;
        const float m_ii = hpii.y * invN;
        const float cov_ip = m_pi - m_p * m_i;
        const float cov_ii = m_ii - m_i * m_i;
        const float a = __fdividef(cov_ip, cov_ii + EPSF);
        const float b = m_p - a * m_i;
        const float icen = sm.i_ring[sy][x];
        const float q = fminf(fmaxf(a * icen + b, 0.0f), 1.0f);
        sm.qbuf[hr][x - RAD] = q;
    }
}

__global__ void __launch_bounds__(BX, 4)
gf_kernel(const float* __restrict__ gI, const float* __restrict__ gP,
          float* __restrict__ gQ)
{
    extern __shared__ unsigned char smem_raw[];
    SmemT& sm = *reinterpret_cast<SmemT*>(smem_raw);

    const int tid = threadIdx.x;
    const int ys  = blockIdx.y * SEGH;
    const int chOff = blockIdx.z * IMH * IMW;
    const float* Ic = gI + chOff;
    const float* Pc = gP + chOff;
    float*       Qc = gQ + chOff;

    const int X0 = blockIdx.x * OUT_W;
    const int c  = X0 - RAD + tid;
    const bool cvalid = (c >= 0) && (c < IMW);
    const bool intx = (X0 >= RAD) && (X0 + OUT_W + RAD <= IMW);

    float vs_i = 0.f, vs_p = 0.f, vs_pi = 0.f, vs_ii = 0.f;

    // Warmup: accumulate rows ys-9 .. ys+7 (17 rows); stash i rows into ring.
    for (int yl = ys - RAD - 1; yl <= ys + RAD - 1; ++yl) {
        float iv = 0.f, pv = 0.f;
        if (yl >= 0 && cvalid) {
            iv = Ic[yl * IMW + c];
            pv = Pc[yl * IMW + c];
        }
        sm.i_ring[(yl + 2 * IRING) % IRING][tid] = iv;
        vs_i += iv; vs_p += pv; vs_pi += iv * pv; vs_ii += iv * iv;
    }

    int sL  = (ys + RAD) % IRING;   // ring slot for leading row y+8
    int y0m = ys % IRING;           // chunk-base slot for HF reads

    const int hr = tid & 15;        // HF row within chunk
    const int hs = tid >> 4;        // HF x-split (8 splits x 14 cols)
    const int xbase = RAD + 14 * hs;

    for (int ck = 0; ck < SEGH / CHUNK; ++ck) {
        const int y0 = ys + ck * CHUNK;

        // ---- V phase: vertical sliding box sums; trailing edge re-read
        // from gmem (L2-resident). Unroll 8 for front-batched LDGs (MLP). ----
        #pragma unroll 8
        for (int r = 0; r < CHUNK; ++r) {
            const int yl = y0 + r + RAD;
            const int yt = y0 + r - RAD - 1;
            float iv = 0.f, pv = 0.f, it = 0.f, pt = 0.f;
            if (yl < IMH && cvalid) {
                iv = __ldg(Ic + yl * IMW + c);
                pv = __ldg(Pc + yl * IMW + c);
            }
            if (yt >= 0 && cvalid) {
                it = __ldg(Ic + yt * IMW + c);
                pt = __ldg(Pc + yt * IMW + c);
            }
            sm.i_ring[sL][tid] = iv;
            vs_i  += iv - it;
            vs_p  += pv - pt;
            vs_pi += iv * pv - it * pt;
            vs_ii += iv * iv - it * it;
            sm.vb_ip [r][tid] = f2_pack(vs_i,  vs_p);
            sm.vb_pii[r][tid] = f2_pack(vs_pi, vs_ii);
            sL = (sL + 1 == IRING) ? 0 : sL + 1;
        }
        __syncthreads();   // B1: vbuf + i_ring ready

        // ---- HF phase (uniform fast-path selection; no divergence) ----
        const bool inty = (y0 >= RAD) && (y0 + CHUNK + RAD <= IMH);
        if (intx && inty) hf_phase<true >(sm, hr, xbase, y0, y0m, X0);
        else              hf_phase<false>(sm, hr, xbase, y0, y0m, X0);
        __syncthreads();   // B2: qbuf ready, vbuf free

        // ---- Q phase: coalesced store; overlaps next chunk's V phase ----
        if (tid < OUT_W && (X0 + tid) < IMW) {
            #pragma unroll 4
            for (int rr = 0; rr < CHUNK; ++rr) {
                Qc[(y0 + rr) * IMW + X0 + tid] = sm.qbuf[rr][tid];
            }
        }

        y0m += CHUNK; if (y0m >= IRING) y0m -= IRING;
    }
}

extern "C" void kernel_launch(void* const* d_in, const int* in_sizes, int n_in,
                              void* d_out, int out_size)
{
    const float* I = (const float*)d_in[0];
    const float* P = (const float*)d_in[1];
    float*       Q = (float*)d_out;

    cudaFuncSetAttribute(gf_kernel, cudaFuncAttributeMaxDynamicSharedMemorySize,
                         (int)sizeof(SmemT));

    dim3 grid(NSTRIPS, NSEG, 3);
    gf_kernel<<<grid, BX, sizeof(SmemT)>>>(I, P, Q);
}

// round 9
// speedup vs baseline: 1.0038x; 1.0038x over previous
#include <cuda_runtime.h>
#include <cuda_bf16.h>

#define IMH 4096
#define IMW 4096
#define RAD 8
#define BX 128
#define OUT_W 112
#define CHUNK 16
#define SEGH 512
#define NSTRIPS ((IMW + OUT_W - 1) / OUT_W)   // 37
#define NSEG (IMH / SEGH)                     // 8
#define EPSF 1e-4f
#define IRING 24

// ~52.6 KB -> 4 CTAs/SM. Odd strides (129/113) keep row-indexed access
// conflict-free; float2 vbuf -> LDS.64 (2 wavefronts, 0 conflicts).
struct SmemT {
    float  i_ring[IRING][BX + 1];   // rows y0..y0+23 of i (HF center reads)
    float2 vb_ip [CHUNK][BX + 1];   // (vsum_i, vsum_p)
    float2 vb_pii[CHUNK][BX + 1];   // (vsum_pi, vsum_ii)
    float  qbuf[CHUNK][OUT_W + 1];  // staged outputs for coalesced store
};

// FAST: whole strip x-interior AND whole chunk y-interior -> N == 289 const.
template<bool FAST>
__device__ __forceinline__ void hf_phase(SmemT& sm, int hr, int xbase,
                                         int y0, int y0m, int X0)
{
    const int y = y0 + hr;
    int sy = y0m + hr; if (sy >= IRING) sy -= IRING;
    int ny = 17;
    if (!FAST) ny = min(y + RAD, IMH - 1) - max(y - RAD, 0) + 1;

    float hi = 0.f, hp = 0.f, hpi = 0.f, hii = 0.f;
    #pragma unroll
    for (int d = -RAD; d <= RAD; ++d) {
        const float2 a2 = sm.vb_ip [hr][xbase + d];
        const float2 b2 = sm.vb_pii[hr][xbase + d];
        hi += a2.x; hp += a2.y; hpi += b2.x; hii += b2.y;
    }
    #pragma unroll
    for (int j = 0; j < 14; ++j) {
        const int x = xbase + j;
        if (j > 0) {
            const float2 aL = sm.vb_ip [hr][x + RAD];
            const float2 aT = sm.vb_ip [hr][x - RAD - 1];
            const float2 bL = sm.vb_pii[hr][x + RAD];
            const float2 bT = sm.vb_pii[hr][x - RAD - 1];
            hi  += aL.x - aT.x; hp  += aL.y - aT.y;
            hpi += bL.x - bT.x; hii += bL.y - bT.y;
        }
        float invN;
        if (FAST) {
            invN = 1.0f / 289.0f;   // compile-time immediate
        } else {
            const int gx = X0 + x - RAD;
            const int nx = min(gx + RAD, IMW - 1) - max(gx - RAD, 0) + 1;
            invN = __fdividef(1.0f, (float)(ny * nx));
        }
        const float m_i  = hi  * invN;
        const float m_p  = hp  * invN;
        const float m_pi = hpi * invN;
        const float m_ii = hii * invN;
        const float cov_ip = m_pi - m_p * m_i;
        const float cov_ii = m_ii - m_i * m_i;
        const float a = __fdividef(cov_ip, cov_ii + EPSF);
        const float b = m_p - a * m_i;
        const float icen = sm.i_ring[sy][x];
        const float q = fminf(fmaxf(a * icen + b, 0.0f), 1.0f);
        sm.qbuf[hr][x - RAD] = q;
    }
}

__global__ void __launch_bounds__(BX, 4)
gf_kernel(const float* __restrict__ gI, const float* __restrict__ gP,
          float* __restrict__ gQ)
{
    extern __shared__ unsigned char smem_raw[];
    SmemT& sm = *reinterpret_cast<SmemT*>(smem_raw);

    const int tid = threadIdx.x;
    const int ys  = blockIdx.y * SEGH;
    const int chOff = blockIdx.z * IMH * IMW;
    const float* Ic = gI + chOff;
    const float* Pc = gP + chOff;
    float*       Qc = gQ + chOff;

    const int X0 = blockIdx.x * OUT_W;
    const int c  = X0 - RAD + tid;
    const bool cvalid = (c >= 0) && (c < IMW);
    const bool intx = (X0 >= RAD) && (X0 + OUT_W + RAD <= IMW);

    float vs_i = 0.f, vs_p = 0.f, vs_pi = 0.f, vs_ii = 0.f;

    // Warmup: accumulate rows ys-9 .. ys+7 (17 rows); stash i rows into ring.
    for (int yl = ys - RAD - 1; yl <= ys + RAD - 1; ++yl) {
        float iv = 0.f, pv = 0.f;
        if (yl >= 0 && cvalid) {
            iv = Ic[yl * IMW + c];
            pv = Pc[yl * IMW + c];
        }
        sm.i_ring[(yl + 2 * IRING) % IRING][tid] = iv;
        vs_i += iv; vs_p += pv; vs_pi += iv * pv; vs_ii += iv * iv;
    }

    int sL  = (ys + RAD) % IRING;   // ring slot for leading row y+8
    int y0m = ys % IRING;           // chunk-base slot for HF reads

    const int hr = tid & 15;        // HF row within chunk
    const int hs = tid >> 4;        // HF x-split (8 splits x 14 cols)
    const int xbase = RAD + 14 * hs;

    for (int ck = 0; ck < SEGH / CHUNK; ++ck) {
        const int y0 = ys + ck * CHUNK;

        // ---- V phase: vertical sliding box sums; trailing edge re-read
        // from gmem (L2-resident). Unroll 8 front-batches LDGs (MLP). ----
        #pragma unroll 8
        for (int r = 0; r < CHUNK; ++r) {
            const int yl = y0 + r + RAD;
            const int yt = y0 + r - RAD - 1;
            float iv = 0.f, pv = 0.f, it = 0.f, pt = 0.f;
            if (yl < IMH && cvalid) {
                iv = __ldg(Ic + yl * IMW + c);
                pv = __ldg(Pc + yl * IMW + c);
            }
            if (yt >= 0 && cvalid) {
                it = __ldg(Ic + yt * IMW + c);
                pt = __ldg(Pc + yt * IMW + c);
            }
            sm.i_ring[sL][tid] = iv;
            vs_i  += iv - it;
            vs_p  += pv - pt;
            vs_pi += iv * pv - it * pt;
            vs_ii += iv * iv - it * it;
            sm.vb_ip [r][tid] = make_float2(vs_i, vs_p);
            sm.vb_pii[r][tid] = make_float2(vs_pi, vs_ii);
            sL = (sL + 1 == IRING) ? 0 : sL + 1;
        }
        __syncthreads();   // B1: vbuf + i_ring ready

        // ---- HF phase (uniform fast-path selection; no divergence) ----
        const bool inty = (y0 >= RAD) && (y0 + CHUNK + RAD <= IMH);
        if (intx && inty) hf_phase<true >(sm, hr, xbase, y0, y0m, X0);
        else              hf_phase<false>(sm, hr, xbase, y0, y0m, X0);
        __syncthreads();   // B2: qbuf ready, vbuf free

        // ---- Q phase: coalesced store; overlaps next chunk's V phase ----
        if (tid < OUT_W && (X0 + tid) < IMW) {
            #pragma unroll 4
            for (int rr = 0; rr < CHUNK; ++rr) {
                Qc[(y0 + rr) * IMW + X0 + tid] = sm.qbuf[rr][tid];
            }
        }

        y0m += CHUNK; if (y0m >= IRING) y0m -= IRING;
    }
}

extern "C" void kernel_launch(void* const* d_in, const int* in_sizes, int n_in,
                              void* d_out, int out_size)
{
    const float* I = (const float*)d_in[0];
    const float* P = (const float*)d_in[1];
    float*       Q = (float*)d_out;

    cudaFuncSetAttribute(gf_kernel, cudaFuncAttributeMaxDynamicSharedMemorySize,
                         (int)sizeof(SmemT));

    dim3 grid(NSTRIPS, NSEG, 3);
    gf_kernel<<<grid, BX, sizeof(SmemT)>>>(I, P, Q);
}

// round 10
// speedup vs baseline: 1.0826x; 1.0785x over previous
#include <cuda_runtime.h>
#include <cuda_bf16.h>

#define IMH 4096
#define IMW 4096
#define RAD 8
#define BX 128
#define OUT_W 112
#define CHUNK 16
#define SEGH 256
#define NSTRIPS ((IMW + OUT_W - 1) / OUT_W)   // 37
#define NSEG (IMH / SEGH)                     // 16 -> grid 37*16*3 = 1776 = 3.0 waves @ 4 CTAs/SM
#define EPSF 1e-4f
#define IRING 24

// ~52.6 KB -> 4 CTAs/SM. Odd strides (129/113) keep row-indexed access
// conflict-free; float2 vbuf -> LDS.64 (2 wavefronts, 0 conflicts).
struct SmemT {
    float  i_ring[IRING][BX + 1];   // rows y0..y0+23 of i (HF center reads)
    float2 vb_ip [CHUNK][BX + 1];   // (vsum_i, vsum_p)
    float2 vb_pii[CHUNK][BX + 1];   // (vsum_pi, vsum_ii)
    float  qbuf[CHUNK][OUT_W + 1];  // staged outputs for coalesced store
};

__global__ void __launch_bounds__(BX, 4)
gf_kernel(const float* __restrict__ gI, const float* __restrict__ gP,
          float* __restrict__ gQ)
{
    extern __shared__ unsigned char smem_raw[];
    SmemT& sm = *reinterpret_cast<SmemT*>(smem_raw);

    const int tid = threadIdx.x;
    const int ys  = blockIdx.y * SEGH;
    const int chOff = blockIdx.z * IMH * IMW;
    const float* Ic = gI + chOff;
    const float* Pc = gP + chOff;
    float*       Qc = gQ + chOff;

    const int X0 = blockIdx.x * OUT_W;
    const int c  = X0 - RAD + tid;
    const bool cvalid = (c >= 0) && (c < IMW);

    float vs_i = 0.f, vs_p = 0.f, vs_pi = 0.f, vs_ii = 0.f;

    // Warmup: accumulate rows ys-9 .. ys+7 (17 rows); stash i rows into ring.
    for (int yl = ys - RAD - 1; yl <= ys + RAD - 1; ++yl) {
        float iv = 0.f, pv = 0.f;
        if (yl >= 0 && cvalid) {
            iv = Ic[yl * IMW + c];
            pv = Pc[yl * IMW + c];
        }
        sm.i_ring[(yl + 2 * IRING) % IRING][tid] = iv;
        vs_i += iv; vs_p += pv; vs_pi += iv * pv; vs_ii += iv * iv;
    }

    int sL  = (ys + RAD) % IRING;   // ring slot for leading row y+8
    int y0m = ys % IRING;           // chunk-base slot for HF reads

    const int hr = tid & 15;        // HF row within chunk
    const int hs = tid >> 4;        // HF x-split (8 splits x 14 cols)
    const int xbase = RAD + 14 * hs;

    for (int ck = 0; ck < SEGH / CHUNK; ++ck) {
        const int y0 = ys + ck * CHUNK;

        // ---- V phase: vertical sliding box sums; trailing edge re-read
        // from gmem (L2-resident). Unroll 8 front-batches LDGs (MLP). ----
        #pragma unroll 8
        for (int r = 0; r < CHUNK; ++r) {
            const int yl = y0 + r + RAD;
            const int yt = y0 + r - RAD - 1;
            float iv = 0.f, pv = 0.f, it = 0.f, pt = 0.f;
            if (yl < IMH && cvalid) {
                iv = __ldg(Ic + yl * IMW + c);
                pv = __ldg(Pc + yl * IMW + c);
            }
            if (yt >= 0 && cvalid) {
                it = __ldg(Ic + yt * IMW + c);
                pt = __ldg(Pc + yt * IMW + c);
            }
            sm.i_ring[sL][tid] = iv;
            vs_i  += iv - it;
            vs_p  += pv - pt;
            vs_pi += iv * pv - it * pt;
            vs_ii += iv * iv - it * it;
            sm.vb_ip [r][tid] = make_float2(vs_i, vs_p);
            sm.vb_pii[r][tid] = make_float2(vs_pi, vs_ii);
            sL = (sL + 1 == IRING) ? 0 : sL + 1;
        }
        __syncthreads();   // B1: vbuf + i_ring ready

        // ---- HF phase: horizontal sliding sums + guided-filter math ----
        {
            const int y = y0 + hr;
            int sy = y0m + hr; if (sy >= IRING) sy -= IRING;
            const int ny = min(y + RAD, IMH - 1) - max(y - RAD, 0) + 1;

            float hi = 0.f, hp = 0.f, hpi = 0.f, hii = 0.f;
            #pragma unroll
            for (int d = -RAD; d <= RAD; ++d) {
                const float2 a2 = sm.vb_ip [hr][xbase + d];
                const float2 b2 = sm.vb_pii[hr][xbase + d];
                hi += a2.x; hp += a2.y; hpi += b2.x; hii += b2.y;
            }
            #pragma unroll
            for (int j = 0; j < 14; ++j) {
                const int x = xbase + j;
                if (j > 0) {
                    const float2 aL = sm.vb_ip [hr][x + RAD];
                    const float2 aT = sm.vb_ip [hr][x - RAD - 1];
                    const float2 bL = sm.vb_pii[hr][x + RAD];
                    const float2 bT = sm.vb_pii[hr][x - RAD - 1];
                    hi  += aL.x - aT.x; hp  += aL.y - aT.y;
                    hpi += bL.x - bT.x; hii += bL.y - bT.y;
                }
                const int gx = X0 + x - RAD;
                const int nx = min(gx + RAD, IMW - 1) - max(gx - RAD, 0) + 1;
                const float invN = __fdividef(1.0f, (float)(ny * nx));

                const float m_i  = hi  * invN;
                const float m_p  = hp  * invN;
                const float m_pi = hpi * invN;
                const float m_ii = hii * invN;
                const float cov_ip = m_pi - m_p * m_i;
                const float cov_ii = m_ii - m_i * m_i;
                const float a = __fdividef(cov_ip, cov_ii + EPSF);
                const float b = m_p - a * m_i;
                const float icen = sm.i_ring[sy][x];
                const float q = fminf(fmaxf(a * icen + b, 0.0f), 1.0f);
                sm.qbuf[hr][x - RAD] = q;
            }
        }
        __syncthreads();   // B2: qbuf ready, vbuf free

        // ---- Q phase: coalesced store; overlaps next chunk's V phase ----
        if (tid < OUT_W && (X0 + tid) < IMW) {
            #pragma unroll 4
            for (int rr = 0; rr < CHUNK; ++rr) {
                Qc[(y0 + rr) * IMW + X0 + tid] = sm.qbuf[rr][tid];
            }
        }

        y0m += CHUNK; if (y0m >= IRING) y0m -= IRING;
    }
}

extern "C" void kernel_launch(void* const* d_in, const int* in_sizes, int n_in,
                              void* d_out, int out_size)
{
    const float* I = (const float*)d_in[0];
    const float* P = (const float*)d_in[1];
    float*       Q = (float*)d_out;

    cudaFuncSetAttribute(gf_kernel, cudaFuncAttributeMaxDynamicSharedMemorySize,
                         (int)sizeof(SmemT));

    dim3 grid(NSTRIPS, NSEG, 3);
    gf_kernel<<<grid, BX, sizeof(SmemT)>>>(I, P, Q);
}